// round 2
// baseline (speedup 1.0000x reference)
#include <cuda_runtime.h>
#include <math.h>

#define NB 8
#define NT 2048
#define NC 1024
#define NH 64
#define QSCALE 0.125f   // 64^-0.5

// Scratch for projections (no allocations allowed in kernel_launch).
__device__ float g_q[NB * NT * NH];
__device__ float g_k[NB * NT * NH];
__device__ float g_v[NB * NT * NH];

// ---------------------------------------------------------------------------
// Projection GEMM: dst = x @ w   (M = NB*NT = 16384, K = NC = 1024, N = NH = 64)
// grid = (M/128, 3), 256 threads. blockIdx.y selects {q,k,v}.
// Thread tile 8x4, BK = 32.
// ---------------------------------------------------------------------------
__global__ __launch_bounds__(256) void proj_kernel(
    const float* __restrict__ x,
    const float* __restrict__ wq,
    const float* __restrict__ wk,
    const float* __restrict__ wv)
{
    __shared__ float sA[32][128];   // x tile, transposed: sA[kk][row]
    __shared__ float sB[32][64];    // w tile: sB[kk][col]

    const float* w   = (blockIdx.y == 0) ? wq : (blockIdx.y == 1) ? wk : wv;
    float*       dst = (blockIdx.y == 0) ? g_q : (blockIdx.y == 1) ? g_k : g_v;

    const int m0  = blockIdx.x * 128;
    const int tid = threadIdx.x;
    const int ty  = tid >> 4;      // 0..15 -> rows ty*8..ty*8+7
    const int tx  = tid & 15;      // 0..15 -> cols tx*4..tx*4+3

    float acc[8][4];
    #pragma unroll
    for (int i = 0; i < 8; i++)
        #pragma unroll
        for (int j = 0; j < 4; j++) acc[i][j] = 0.f;

    for (int k0 = 0; k0 < NC; k0 += 32) {
        // Load x tile 128x32 (1024 float4, 4 per thread), store transposed.
        #pragma unroll
        for (int u = 0; u < 4; u++) {
            int f  = tid * 4 + u;          // 0..1023
            int r  = f >> 3;               // row 0..127
            int c4 = f & 7;                // float4 index within 32-wide row
            float4 t = *(const float4*)&x[(size_t)(m0 + r) * NC + k0 + c4 * 4];
            sA[c4 * 4 + 0][r] = t.x;
            sA[c4 * 4 + 1][r] = t.y;
            sA[c4 * 4 + 2][r] = t.z;
            sA[c4 * 4 + 3][r] = t.w;
        }
        // Load w tile 32x64 (512 float4, 2 per thread).
        #pragma unroll
        for (int u = 0; u < 2; u++) {
            int f  = tid * 2 + u;          // 0..511
            int r  = f >> 4;               // 0..31
            int c4 = f & 15;
            float4 t = *(const float4*)&w[(size_t)(k0 + r) * NH + c4 * 4];
            *(float4*)&sB[r][c4 * 4] = t;
        }
        __syncthreads();

        #pragma unroll
        for (int kk = 0; kk < 32; kk++) {
            float a[8], b[4];
            #pragma unroll
            for (int i = 0; i < 8; i++) a[i] = sA[kk][ty * 8 + i];
            #pragma unroll
            for (int j = 0; j < 4; j++) b[j] = sB[kk][tx * 4 + j];
            #pragma unroll
            for (int i = 0; i < 8; i++)
                #pragma unroll
                for (int j = 0; j < 4; j++)
                    acc[i][j] = fmaf(a[i], b[j], acc[i][j]);
        }
        __syncthreads();
    }

    #pragma unroll
    for (int i = 0; i < 8; i++) {
        int r = m0 + ty * 8 + i;
        float4 t = make_float4(acc[i][0], acc[i][1], acc[i][2], acc[i][3]);
        *(float4*)&dst[(size_t)r * NH + tx * 4] = t;
    }
}

// ---------------------------------------------------------------------------
// Causal flash attention: grid = (T/64, B), 256 threads, 64-query tiles.
// Dynamic smem: Q/K/V/S tiles (65-float pitch) + m/l/alpha.
// ---------------------------------------------------------------------------
#define PITCH 65
struct AttnSmem {
    float q[64][PITCH];
    float k[64][PITCH];
    float v[64][PITCH];
    float s[64][PITCH];
    float m[64];
    float l[64];
    float alpha[64];
};

extern __shared__ char attn_smem_raw[];

__global__ __launch_bounds__(256) void attn_kernel(float* __restrict__ out)
{
    AttnSmem* sm = reinterpret_cast<AttnSmem*>(attn_smem_raw);

    const int b   = blockIdx.y;
    const int it  = blockIdx.x;          // query tile index
    const int tid = threadIdx.x;
    const int ty  = tid >> 4;            // 0..15 -> rows ty*4..ty*4+3
    const int tx  = tid & 15;            // 0..15 -> cols tx*4..tx*4+3

    const float* Qb = g_q + (size_t)b * NT * NH;
    const float* Kb = g_k + (size_t)b * NT * NH;
    const float* Vb = g_v + (size_t)b * NT * NH;

    if (tid < 64) { sm->m[tid] = -INFINITY; sm->l[tid] = 0.f; }

    // Load Q tile (4096 floats = 1024 float4, 4 per thread).
    #pragma unroll
    for (int u = 0; u < 4; u++) {
        int f  = tid * 4 + u;
        int r  = f >> 4;
        int c4 = f & 15;
        float4 t = *(const float4*)&Qb[(size_t)(it * 64 + r) * NH + c4 * 4];
        sm->q[r][c4 * 4 + 0] = t.x;
        sm->q[r][c4 * 4 + 1] = t.y;
        sm->q[r][c4 * 4 + 2] = t.z;
        sm->q[r][c4 * 4 + 3] = t.w;
    }

    float o[4][4];
    #pragma unroll
    for (int i = 0; i < 4; i++)
        #pragma unroll
        for (int j = 0; j < 4; j++) o[i][j] = 0.f;

    for (int jt = 0; jt <= it; jt++) {
        // Load K, V tiles.
        #pragma unroll
        for (int u = 0; u < 4; u++) {
            int f  = tid * 4 + u;
            int r  = f >> 4;
            int c4 = f & 15;
            size_t gbase = (size_t)(jt * 64 + r) * NH + c4 * 4;
            float4 tk = *(const float4*)&Kb[gbase];
            float4 tv = *(const float4*)&Vb[gbase];
            sm->k[r][c4 * 4 + 0] = tk.x;
            sm->k[r][c4 * 4 + 1] = tk.y;
            sm->k[r][c4 * 4 + 2] = tk.z;
            sm->k[r][c4 * 4 + 3] = tk.w;
            sm->v[r][c4 * 4 + 0] = tv.x;
            sm->v[r][c4 * 4 + 1] = tv.y;
            sm->v[r][c4 * 4 + 2] = tv.z;
            sm->v[r][c4 * 4 + 3] = tv.w;
        }
        __syncthreads();

        // S = Q @ K^T (4x4 per thread over 64-dim dot).
        float acc[4][4];
        #pragma unroll
        for (int i = 0; i < 4; i++)
            #pragma unroll
            for (int j = 0; j < 4; j++) acc[i][j] = 0.f;
        #pragma unroll
        for (int kk = 0; kk < 64; kk++) {
            float a[4], bb[4];
            #pragma unroll
            for (int i = 0; i < 4; i++) a[i]  = sm->q[ty * 4 + i][kk];
            #pragma unroll
            for (int j = 0; j < 4; j++) bb[j] = sm->k[tx * 4 + j][kk];
            #pragma unroll
            for (int i = 0; i < 4; i++)
                #pragma unroll
                for (int j = 0; j < 4; j++)
                    acc[i][j] = fmaf(a[i], bb[j], acc[i][j]);
        }
        // Scale + causal mask, stage to smem.
        #pragma unroll
        for (int i = 0; i < 4; i++) {
            int qi = it * 64 + ty * 4 + i;
            #pragma unroll
            for (int j = 0; j < 4; j++) {
                int kj = jt * 64 + tx * 4 + j;
                sm->s[ty * 4 + i][tx * 4 + j] =
                    (kj <= qi) ? acc[i][j] * QSCALE : -INFINITY;
            }
        }
        __syncthreads();

        // Online softmax, one thread per row.
        if (tid < 64) {
            int r = tid;
            float mo = sm->m[r];
            float mn = mo;
            #pragma unroll
            for (int c = 0; c < 64; c++) mn = fmaxf(mn, sm->s[r][c]);
            float al = __expf(mo - mn);      // 0 when mo = -inf
            float ls = sm->l[r] * al;
            #pragma unroll
            for (int c = 0; c < 64; c++) {
                float p = __expf(sm->s[r][c] - mn);   // 0 for masked entries
                sm->s[r][c] = p;
                ls += p;
            }
            sm->m[r] = mn;
            sm->l[r] = ls;
            sm->alpha[r] = al;
        }
        __syncthreads();

        // O = O * alpha + P @ V.
        float al[4];
        #pragma unroll
        for (int i = 0; i < 4; i++) al[i] = sm->alpha[ty * 4 + i];
        #pragma unroll
        for (int i = 0; i < 4; i++)
            #pragma unroll
            for (int j = 0; j < 4; j++) o[i][j] *= al[i];
        #pragma unroll
        for (int kk = 0; kk < 64; kk++) {
            float p[4], vv[4];
            #pragma unroll
            for (int i = 0; i < 4; i++) p[i]  = sm->s[ty * 4 + i][kk];
            #pragma unroll
            for (int j = 0; j < 4; j++) vv[j] = sm->v[kk][tx * 4 + j];
            #pragma unroll
            for (int i = 0; i < 4; i++)
                #pragma unroll
                for (int j = 0; j < 4; j++)
                    o[i][j] = fmaf(p[i], vv[j], o[i][j]);
        }
        __syncthreads();   // protect K/V/S before next tile overwrites
    }

    // Normalize and write out.
    #pragma unroll
    for (int i = 0; i < 4; i++) {
        float inv = 1.f / sm->l[ty * 4 + i];
        float4 t = make_float4(o[i][0] * inv, o[i][1] * inv,
                               o[i][2] * inv, o[i][3] * inv);
        size_t row = (size_t)b * NT + it * 64 + ty * 4 + i;
        *(float4*)&out[row * NH + tx * 4] = t;
    }
}

// ---------------------------------------------------------------------------

extern "C" void kernel_launch(void* const* d_in, const int* in_sizes, int n_in,
                              void* d_out, int out_size)
{
    const float* x  = (const float*)d_in[0];
    const float* wq = (const float*)d_in[1];
    const float* wk = (const float*)d_in[2];
    const float* wv = (const float*)d_in[3];
    float* out = (float*)d_out;

    const int smem_bytes = (int)sizeof(AttnSmem);
    cudaFuncSetAttribute(attn_kernel,
                         cudaFuncAttributeMaxDynamicSharedMemorySize,
                         smem_bytes);

    proj_kernel<<<dim3((NB * NT) / 128, 3), 256>>>(x, wq, wk, wv);
    attn_kernel<<<dim3(NT / 64, NB), 256, smem_bytes>>>(out);
}

// round 3
// speedup vs baseline: 1.0568x; 1.0568x over previous
#include <cuda_runtime.h>
#include <math.h>

#define NB 8
#define NT 2048
#define NC 1024
#define NH 64
#define QSCALE 0.125f   // 64^-0.5

// Scratch for projections (no allocations allowed in kernel_launch).
__device__ float g_q[NB * NT * NH];
__device__ float g_k[NB * NT * NH];
__device__ float g_v[NB * NT * NH];

// ---------------------------------------------------------------------------
// Projection GEMM: dst = x @ w   (M = NB*NT = 16384, K = NC = 1024, N = NH = 64)
// grid = (M/128, 3), 256 threads. blockIdx.y selects {q,k,v}.
// ---------------------------------------------------------------------------
__global__ __launch_bounds__(256) void proj_kernel(
    const float* __restrict__ x,
    const float* __restrict__ wq,
    const float* __restrict__ wk,
    const float* __restrict__ wv)
{
    __shared__ float sA[32][128];   // x tile, transposed: sA[kk][row]
    __shared__ float sB[32][64];    // w tile: sB[kk][col]

    const float* w   = (blockIdx.y == 0) ? wq : (blockIdx.y == 1) ? wk : wv;
    float*       dst = (blockIdx.y == 0) ? g_q : (blockIdx.y == 1) ? g_k : g_v;

    const int m0  = blockIdx.x * 128;
    const int tid = threadIdx.x;
    const int ty  = tid >> 4;      // 0..15 -> rows ty*8..ty*8+7
    const int tx  = tid & 15;      // 0..15 -> cols tx*4..tx*4+3

    float acc[8][4];
    #pragma unroll
    for (int i = 0; i < 8; i++)
        #pragma unroll
        for (int j = 0; j < 4; j++) acc[i][j] = 0.f;

    for (int k0 = 0; k0 < NC; k0 += 32) {
        #pragma unroll
        for (int u = 0; u < 4; u++) {
            int f  = tid * 4 + u;
            int r  = f >> 3;
            int c4 = f & 7;
            float4 t = *(const float4*)&x[(size_t)(m0 + r) * NC + k0 + c4 * 4];
            sA[c4 * 4 + 0][r] = t.x;
            sA[c4 * 4 + 1][r] = t.y;
            sA[c4 * 4 + 2][r] = t.z;
            sA[c4 * 4 + 3][r] = t.w;
        }
        #pragma unroll
        for (int u = 0; u < 2; u++) {
            int f  = tid * 2 + u;
            int r  = f >> 4;
            int c4 = f & 15;
            float4 t = *(const float4*)&w[(size_t)(k0 + r) * NH + c4 * 4];
            *(float4*)&sB[r][c4 * 4] = t;
        }
        __syncthreads();

        #pragma unroll
        for (int kk = 0; kk < 32; kk++) {
            float a[8], b[4];
            #pragma unroll
            for (int i = 0; i < 8; i++) a[i] = sA[kk][ty * 8 + i];
            #pragma unroll
            for (int j = 0; j < 4; j++) b[j] = sB[kk][tx * 4 + j];
            #pragma unroll
            for (int i = 0; i < 8; i++)
                #pragma unroll
                for (int j = 0; j < 4; j++)
                    acc[i][j] = fmaf(a[i], b[j], acc[i][j]);
        }
        __syncthreads();
    }

    #pragma unroll
    for (int i = 0; i < 8; i++) {
        int r = m0 + ty * 8 + i;
        float4 t = make_float4(acc[i][0], acc[i][1], acc[i][2], acc[i][3]);
        *(float4*)&dst[(size_t)r * NH + tx * 4] = t;
    }
}

// ---------------------------------------------------------------------------
// Causal flash attention v2: register softmax + shfl row reductions.
// grid = (T/64, B), 256 threads, 64-query tiles.
// ---------------------------------------------------------------------------
#define PITCH 65
struct AttnSmem {
    float q[64][PITCH];
    float k[64][PITCH];
    float v[64][PITCH];
    float s[64][PITCH];   // holds P (post-exp probabilities)
};

extern __shared__ char attn_smem_raw[];

__global__ __launch_bounds__(256) void attn_kernel(float* __restrict__ out)
{
    AttnSmem* sm = reinterpret_cast<AttnSmem*>(attn_smem_raw);

    const int b   = blockIdx.y;
    const int it  = gridDim.x - 1 - blockIdx.x;   // heaviest tiles launch first
    const int tid = threadIdx.x;
    const int ty  = tid >> 4;            // rows ty*4..ty*4+3
    const int tx  = tid & 15;            // cols tx*4..tx*4+3

    const float* Qb = g_q + (size_t)b * NT * NH;
    const float* Kb = g_k + (size_t)b * NT * NH;
    const float* Vb = g_v + (size_t)b * NT * NH;

    // Load Q tile (1024 float4, 4 per thread).
    #pragma unroll
    for (int u = 0; u < 4; u++) {
        int f  = tid * 4 + u;
        int r  = f >> 4;
        int c4 = f & 15;
        float4 t = *(const float4*)&Qb[(size_t)(it * 64 + r) * NH + c4 * 4];
        sm->q[r][c4 * 4 + 0] = t.x;
        sm->q[r][c4 * 4 + 1] = t.y;
        sm->q[r][c4 * 4 + 2] = t.z;
        sm->q[r][c4 * 4 + 3] = t.w;
    }

    float o[4][4];
    float m[4], l[4];
    #pragma unroll
    for (int i = 0; i < 4; i++) {
        m[i] = -INFINITY;
        l[i] = 0.f;
        #pragma unroll
        for (int j = 0; j < 4; j++) o[i][j] = 0.f;
    }

    for (int jt = 0; jt <= it; jt++) {
        // Load K, V tiles.
        #pragma unroll
        for (int u = 0; u < 4; u++) {
            int f  = tid * 4 + u;
            int r  = f >> 4;
            int c4 = f & 15;
            size_t gbase = (size_t)(jt * 64 + r) * NH + c4 * 4;
            float4 tk = *(const float4*)&Kb[gbase];
            float4 tv = *(const float4*)&Vb[gbase];
            sm->k[r][c4 * 4 + 0] = tk.x;
            sm->k[r][c4 * 4 + 1] = tk.y;
            sm->k[r][c4 * 4 + 2] = tk.z;
            sm->k[r][c4 * 4 + 3] = tk.w;
            sm->v[r][c4 * 4 + 0] = tv.x;
            sm->v[r][c4 * 4 + 1] = tv.y;
            sm->v[r][c4 * 4 + 2] = tv.z;
            sm->v[r][c4 * 4 + 3] = tv.w;
        }
        __syncthreads();

        // S = Q @ K^T, scaled.
        float acc[4][4];
        #pragma unroll
        for (int i = 0; i < 4; i++)
            #pragma unroll
            for (int j = 0; j < 4; j++) acc[i][j] = 0.f;
        #pragma unroll
        for (int kk = 0; kk < 64; kk++) {
            float a[4], bb[4];
            #pragma unroll
            for (int i = 0; i < 4; i++) a[i]  = sm->q[ty * 4 + i][kk];
            #pragma unroll
            for (int j = 0; j < 4; j++) bb[j] = sm->k[tx * 4 + j][kk];
            #pragma unroll
            for (int i = 0; i < 4; i++)
                #pragma unroll
                for (int j = 0; j < 4; j++)
                    acc[i][j] = fmaf(a[i], bb[j], acc[i][j]);
        }
        #pragma unroll
        for (int i = 0; i < 4; i++)
            #pragma unroll
            for (int j = 0; j < 4; j++) acc[i][j] *= QSCALE;

        // Causal mask only on the diagonal tile.
        if (jt == it) {
            #pragma unroll
            for (int i = 0; i < 4; i++) {
                int qi = ty * 4 + i;
                #pragma unroll
                for (int j = 0; j < 4; j++) {
                    if (tx * 4 + j > qi) acc[i][j] = -INFINITY;
                }
            }
        }

        // Row max via shfl butterfly over tx (lanes 0-15 / 16-31 halves).
        float mn[4], alpha[4];
        #pragma unroll
        for (int i = 0; i < 4; i++) {
            float v = fmaxf(fmaxf(acc[i][0], acc[i][1]),
                            fmaxf(acc[i][2], acc[i][3]));
            #pragma unroll
            for (int d = 1; d < 16; d <<= 1)
                v = fmaxf(v, __shfl_xor_sync(0xffffffffu, v, d));
            mn[i] = fmaxf(m[i], v);
            alpha[i] = __expf(m[i] - mn[i]);   // 0 on first tile
            m[i] = mn[i];
        }

        // P = exp(S - m), row sums via shfl; write P to smem.
        #pragma unroll
        for (int i = 0; i < 4; i++) {
            float p0 = __expf(acc[i][0] - mn[i]);
            float p1 = __expf(acc[i][1] - mn[i]);
            float p2 = __expf(acc[i][2] - mn[i]);
            float p3 = __expf(acc[i][3] - mn[i]);
            sm->s[ty * 4 + i][tx * 4 + 0] = p0;
            sm->s[ty * 4 + i][tx * 4 + 1] = p1;
            sm->s[ty * 4 + i][tx * 4 + 2] = p2;
            sm->s[ty * 4 + i][tx * 4 + 3] = p3;
            float rs = (p0 + p1) + (p2 + p3);
            #pragma unroll
            for (int d = 1; d < 16; d <<= 1)
                rs += __shfl_xor_sync(0xffffffffu, rs, d);
            l[i] = l[i] * alpha[i] + rs;
            #pragma unroll
            for (int j = 0; j < 4; j++) o[i][j] *= alpha[i];
        }
        __syncthreads();

        // O += P @ V.
        #pragma unroll
        for (int kk = 0; kk < 64; kk++) {
            float p[4], vv[4];
            #pragma unroll
            for (int i = 0; i < 4; i++) p[i]  = sm->s[ty * 4 + i][kk];
            #pragma unroll
            for (int j = 0; j < 4; j++) vv[j] = sm->v[kk][tx * 4 + j];
            #pragma unroll
            for (int i = 0; i < 4; i++)
                #pragma unroll
                for (int j = 0; j < 4; j++)
                    o[i][j] = fmaf(p[i], vv[j], o[i][j]);
        }
        __syncthreads();   // protect k/v/s before next tile overwrites
    }

    // Normalize and write out (l replicated across tx threads).
    #pragma unroll
    for (int i = 0; i < 4; i++) {
        float inv = 1.f / l[i];
        float4 t = make_float4(o[i][0] * inv, o[i][1] * inv,
                               o[i][2] * inv, o[i][3] * inv);
        size_t row = (size_t)b * NT + it * 64 + ty * 4 + i;
        *(float4*)&out[row * NH + tx * 4] = t;
    }
}

// ---------------------------------------------------------------------------

extern "C" void kernel_launch(void* const* d_in, const int* in_sizes, int n_in,
                              void* d_out, int out_size)
{
    const float* x  = (const float*)d_in[0];
    const float* wq = (const float*)d_in[1];
    const float* wk = (const float*)d_in[2];
    const float* wv = (const float*)d_in[3];
    float* out = (float*)d_out;

    const int smem_bytes = (int)sizeof(AttnSmem);
    cudaFuncSetAttribute(attn_kernel,
                         cudaFuncAttributeMaxDynamicSharedMemorySize,
                         smem_bytes);

    proj_kernel<<<dim3((NB * NT) / 128, 3), 256>>>(x, wq, wk, wv);
    attn_kernel<<<dim3(NT / 64, NB), 256, smem_bytes>>>(out);
}

// round 4
// speedup vs baseline: 1.6630x; 1.5737x over previous
#include <cuda_runtime.h>
#include <math.h>

#define NB 8
#define NT 2048
#define NC 1024
#define NH 64
#define QSCALE 0.125f   // 64^-0.5
#define NTILES (NT / 64) // 32

// Scratch for projections.
__device__ float g_q[NB * NT * NH];
__device__ float g_k[NB * NT * NH];
__device__ float g_v[NB * NT * NH];

// ---------------------------------------------------------------------------
// Fused projection GEMM: {q,k,v} = x @ {wq,wk,wv}
// M = 16384, K = 1024, N = 192 (3x64). Block tile 128x192, thread tile 8x12.
// grid = 128 blocks, 256 threads. Double-buffered BK=16 with LDG prefetch.
// ---------------------------------------------------------------------------
#define PBK 16
#define PAP 132   // 128 + 4 pad
#define PBP 196   // 192 + 4 pad

__global__ __launch_bounds__(256) void proj_kernel(
    const float* __restrict__ x,
    const float* __restrict__ wq,
    const float* __restrict__ wk,
    const float* __restrict__ wv)
{
    __shared__ float sA[2][PBK][PAP];   // x tile transposed: sA[kk][row]
    __shared__ float sB[2][PBK][PBP];   // w tile: sB[kk][col], col 0..191

    const int m0  = blockIdx.x * 128;
    const int tid = threadIdx.x;
    const int tr  = tid >> 4;      // 0..15 -> rows tr*8..tr*8+7
    const int tc  = tid & 15;      // 0..15 -> cols tc*12..tc*12+11

    const float* wsel[3] = {wq, wk, wv};
    float*       dsel[3] = {g_q, g_k, g_v};

    float acc[8][12];
    #pragma unroll
    for (int i = 0; i < 8; i++)
        #pragma unroll
        for (int j = 0; j < 12; j++) acc[i][j] = 0.f;

    // ---- load first k-step into buffer 0 ----
    float4 ar[2], br[3];
    #pragma unroll
    for (int u = 0; u < 2; u++) {
        int f = tid * 2 + u;              // 0..511
        int r = f >> 2, c4 = f & 3;
        ar[u] = *(const float4*)&x[(size_t)(m0 + r) * NC + c4 * 4];
    }
    #pragma unroll
    for (int u = 0; u < 3; u++) {
        int f  = tid * 3 + u;             // 0..767
        int kk = f / 48, c4 = f % 48;
        int col = c4 * 4;
        br[u] = *(const float4*)&wsel[col >> 6][(size_t)kk * NH + (col & 63)];
    }
    #pragma unroll
    for (int u = 0; u < 2; u++) {
        int f = tid * 2 + u;
        int r = f >> 2, c4 = f & 3;
        sA[0][c4 * 4 + 0][r] = ar[u].x;
        sA[0][c4 * 4 + 1][r] = ar[u].y;
        sA[0][c4 * 4 + 2][r] = ar[u].z;
        sA[0][c4 * 4 + 3][r] = ar[u].w;
    }
    #pragma unroll
    for (int u = 0; u < 3; u++) {
        int f  = tid * 3 + u;
        int kk = f / 48, c4 = f % 48;
        *(float4*)&sB[0][kk][c4 * 4] = br[u];
    }
    __syncthreads();

    const int NSTEP = NC / PBK;   // 64
    for (int ks = 0; ks < NSTEP; ks++) {
        int cur = ks & 1;
        // prefetch next k-step into registers
        if (ks + 1 < NSTEP) {
            int k0 = (ks + 1) * PBK;
            #pragma unroll
            for (int u = 0; u < 2; u++) {
                int f = tid * 2 + u;
                int r = f >> 2, c4 = f & 3;
                ar[u] = *(const float4*)&x[(size_t)(m0 + r) * NC + k0 + c4 * 4];
            }
            #pragma unroll
            for (int u = 0; u < 3; u++) {
                int f  = tid * 3 + u;
                int kk = f / 48, c4 = f % 48;
                int col = c4 * 4;
                br[u] = *(const float4*)&wsel[col >> 6][(size_t)(k0 + kk) * NH + (col & 63)];
            }
        }
        // compute on current buffer
        #pragma unroll
        for (int kk = 0; kk < PBK; kk++) {
            float a[8], b[12];
            *(float4*)&a[0] = *(float4*)&sA[cur][kk][tr * 8];
            *(float4*)&a[4] = *(float4*)&sA[cur][kk][tr * 8 + 4];
            *(float4*)&b[0] = *(float4*)&sB[cur][kk][tc * 12];
            *(float4*)&b[4] = *(float4*)&sB[cur][kk][tc * 12 + 4];
            *(float4*)&b[8] = *(float4*)&sB[cur][kk][tc * 12 + 8];
            #pragma unroll
            for (int i = 0; i < 8; i++)
                #pragma unroll
                for (int j = 0; j < 12; j++)
                    acc[i][j] = fmaf(a[i], b[j], acc[i][j]);
        }
        // store prefetched data into the other buffer
        if (ks + 1 < NSTEP) {
            int nxt = cur ^ 1;
            #pragma unroll
            for (int u = 0; u < 2; u++) {
                int f = tid * 2 + u;
                int r = f >> 2, c4 = f & 3;
                sA[nxt][c4 * 4 + 0][r] = ar[u].x;
                sA[nxt][c4 * 4 + 1][r] = ar[u].y;
                sA[nxt][c4 * 4 + 2][r] = ar[u].z;
                sA[nxt][c4 * 4 + 3][r] = ar[u].w;
            }
            #pragma unroll
            for (int u = 0; u < 3; u++) {
                int f  = tid * 3 + u;
                int kk = f / 48, c4 = f % 48;
                *(float4*)&sB[nxt][kk][c4 * 4] = br[u];
            }
        }
        __syncthreads();
    }

    // write out: 3 float4 groups per row, each group within one matrix
    #pragma unroll
    for (int i = 0; i < 8; i++) {
        int r = m0 + tr * 8 + i;
        #pragma unroll
        for (int g = 0; g < 3; g++) {
            int col = tc * 12 + g * 4;
            float* dst = dsel[col >> 6];
            float4 t = make_float4(acc[i][g*4+0], acc[i][g*4+1],
                                   acc[i][g*4+2], acc[i][g*4+3]);
            *(float4*)&dst[(size_t)r * NH + (col & 63)] = t;
        }
    }
}

// ---------------------------------------------------------------------------
// Causal flash attention v3:
//   - block handles query-tile pair (p, 31-p): exactly 33 KV-tile units
//   - transposed Q/K in smem -> LDS.128 operands
//   - double-buffered K/V with register prefetch, 1 block barrier per KV tile
//   - P staging is half-warp local -> __syncwarp only
// grid = (16, 8), 256 threads.
// ---------------------------------------------------------------------------
#define PITCH 68
struct AttnSmem {
    float qT[64][PITCH];     // qT[h][row], pre-scaled by QSCALE
    float kT[2][64][PITCH];  // kT[h][col]
    float v [2][64][PITCH];  // v[token][h]
    float s [64][PITCH];     // P probabilities
};

extern __shared__ char attn_smem_raw[];

__device__ __forceinline__ void attn_tile(
    AttnSmem* sm, const float* Qb, const float* Kb, const float* Vb,
    float* out, int b, int it, int tid, int ty, int tx)
{
    // ---- load Q tile transposed, pre-scaled ----
    #pragma unroll
    for (int u = 0; u < 4; u++) {
        int f  = tid * 4 + u;
        int r  = f >> 4;
        int c4 = f & 15;
        float4 t = *(const float4*)&Qb[(size_t)(it * 64 + r) * NH + c4 * 4];
        sm->qT[c4 * 4 + 0][r] = t.x * QSCALE;
        sm->qT[c4 * 4 + 1][r] = t.y * QSCALE;
        sm->qT[c4 * 4 + 2][r] = t.z * QSCALE;
        sm->qT[c4 * 4 + 3][r] = t.w * QSCALE;
    }
    // ---- prefetch KV tile 0 into buffer 0 ----
    {
        #pragma unroll
        for (int u = 0; u < 4; u++) {
            int f  = tid * 4 + u;
            int r  = f >> 4;
            int c4 = f & 15;
            size_t gb = (size_t)r * NH + c4 * 4;
            float4 tk = *(const float4*)&Kb[gb];
            float4 tv = *(const float4*)&Vb[gb];
            sm->kT[0][c4 * 4 + 0][r] = tk.x;
            sm->kT[0][c4 * 4 + 1][r] = tk.y;
            sm->kT[0][c4 * 4 + 2][r] = tk.z;
            sm->kT[0][c4 * 4 + 3][r] = tk.w;
            *(float4*)&sm->v[0][r][c4 * 4] = tv;
        }
    }
    __syncthreads();

    float o[4][4];
    float m[4], l[4];
    #pragma unroll
    for (int i = 0; i < 4; i++) {
        m[i] = -INFINITY; l[i] = 0.f;
        #pragma unroll
        for (int j = 0; j < 4; j++) o[i][j] = 0.f;
    }

    for (int jt = 0; jt <= it; jt++) {
        int cur = jt & 1;
        // prefetch next KV tile into registers
        float4 kr[4], vr[4];
        if (jt < it) {
            #pragma unroll
            for (int u = 0; u < 4; u++) {
                int f  = tid * 4 + u;
                int r  = f >> 4;
                int c4 = f & 15;
                size_t gb = (size_t)((jt + 1) * 64 + r) * NH + c4 * 4;
                kr[u] = *(const float4*)&Kb[gb];
                vr[u] = *(const float4*)&Vb[gb];
            }
        }

        // ---- S = Q @ K^T (pre-scaled) ----
        float acc[4][4];
        #pragma unroll
        for (int i = 0; i < 4; i++)
            #pragma unroll
            for (int j = 0; j < 4; j++) acc[i][j] = 0.f;
        #pragma unroll
        for (int kk = 0; kk < 64; kk++) {
            float4 a = *(float4*)&sm->qT[kk][ty * 4];
            float4 bb = *(float4*)&sm->kT[cur][kk][tx * 4];
            float av[4] = {a.x, a.y, a.z, a.w};
            float bv[4] = {bb.x, bb.y, bb.z, bb.w};
            #pragma unroll
            for (int i = 0; i < 4; i++)
                #pragma unroll
                for (int j = 0; j < 4; j++)
                    acc[i][j] = fmaf(av[i], bv[j], acc[i][j]);
        }

        // causal mask on diagonal tile only
        if (jt == it) {
            #pragma unroll
            for (int i = 0; i < 4; i++) {
                int qi = ty * 4 + i;
                #pragma unroll
                for (int j = 0; j < 4; j++)
                    if (tx * 4 + j > qi) acc[i][j] = -INFINITY;
            }
        }

        // ---- online softmax (half-warp local) ----
        float mn[4], alpha[4];
        #pragma unroll
        for (int i = 0; i < 4; i++) {
            float v = fmaxf(fmaxf(acc[i][0], acc[i][1]),
                            fmaxf(acc[i][2], acc[i][3]));
            #pragma unroll
            for (int d = 1; d < 16; d <<= 1)
                v = fmaxf(v, __shfl_xor_sync(0xffffffffu, v, d));
            mn[i] = fmaxf(m[i], v);
            alpha[i] = __expf(m[i] - mn[i]);
            m[i] = mn[i];
        }
        #pragma unroll
        for (int i = 0; i < 4; i++) {
            float p0 = __expf(acc[i][0] - mn[i]);
            float p1 = __expf(acc[i][1] - mn[i]);
            float p2 = __expf(acc[i][2] - mn[i]);
            float p3 = __expf(acc[i][3] - mn[i]);
            *(float4*)&sm->s[ty * 4 + i][tx * 4] = make_float4(p0, p1, p2, p3);
            float rs = (p0 + p1) + (p2 + p3);
            #pragma unroll
            for (int d = 1; d < 16; d <<= 1)
                rs += __shfl_xor_sync(0xffffffffu, rs, d);
            l[i] = l[i] * alpha[i] + rs;
            #pragma unroll
            for (int j = 0; j < 4; j++) o[i][j] *= alpha[i];
        }
        __syncwarp();   // P visible within half-warp

        // ---- O += P @ V ----
        #pragma unroll
        for (int kk = 0; kk < 64; kk++) {
            float p[4];
            #pragma unroll
            for (int i = 0; i < 4; i++) p[i] = sm->s[ty * 4 + i][kk];
            float4 vv4 = *(float4*)&sm->v[cur][kk][tx * 4];
            float vv[4] = {vv4.x, vv4.y, vv4.z, vv4.w};
            #pragma unroll
            for (int i = 0; i < 4; i++)
                #pragma unroll
                for (int j = 0; j < 4; j++)
                    o[i][j] = fmaf(p[i], vv[j], o[i][j]);
        }

        // store prefetched KV into other buffer
        if (jt < it) {
            int nxt = cur ^ 1;
            #pragma unroll
            for (int u = 0; u < 4; u++) {
                int f  = tid * 4 + u;
                int r  = f >> 4;
                int c4 = f & 15;
                sm->kT[nxt][c4 * 4 + 0][r] = kr[u].x;
                sm->kT[nxt][c4 * 4 + 1][r] = kr[u].y;
                sm->kT[nxt][c4 * 4 + 2][r] = kr[u].z;
                sm->kT[nxt][c4 * 4 + 3][r] = kr[u].w;
                *(float4*)&sm->v[nxt][r][c4 * 4] = vr[u];
            }
        }
        __syncthreads();
    }

    // ---- normalize and write ----
    #pragma unroll
    for (int i = 0; i < 4; i++) {
        float inv = 1.f / l[i];
        float4 t = make_float4(o[i][0] * inv, o[i][1] * inv,
                               o[i][2] * inv, o[i][3] * inv);
        size_t row = (size_t)b * NT + it * 64 + ty * 4 + i;
        *(float4*)&out[row * NH + tx * 4] = t;
    }
}

__global__ __launch_bounds__(256) void attn_kernel(float* __restrict__ out)
{
    AttnSmem* sm = reinterpret_cast<AttnSmem*>(attn_smem_raw);

    const int b   = blockIdx.y;
    const int p   = blockIdx.x;          // pair index 0..15
    const int tid = threadIdx.x;
    const int ty  = tid >> 4;
    const int tx  = tid & 15;

    const float* Qb = g_q + (size_t)b * NT * NH;
    const float* Kb = g_k + (size_t)b * NT * NH;
    const float* Vb = g_v + (size_t)b * NT * NH;

    // heavy tile first, then light tile: total = exactly 33 units per block
    attn_tile(sm, Qb, Kb, Vb, out, b, NTILES - 1 - p, tid, ty, tx);
    __syncthreads();
    attn_tile(sm, Qb, Kb, Vb, out, b, p, tid, ty, tx);
}

// ---------------------------------------------------------------------------

extern "C" void kernel_launch(void* const* d_in, const int* in_sizes, int n_in,
                              void* d_out, int out_size)
{
    const float* x  = (const float*)d_in[0];
    const float* wq = (const float*)d_in[1];
    const float* wk = (const float*)d_in[2];
    const float* wv = (const float*)d_in[3];
    float* out = (float*)d_out;

    const int smem_bytes = (int)sizeof(AttnSmem);
    cudaFuncSetAttribute(attn_kernel,
                         cudaFuncAttributeMaxDynamicSharedMemorySize,
                         smem_bytes);

    proj_kernel<<<dim3((NB * NT) / 128), 256>>>(x, wq, wk, wv);
    attn_kernel<<<dim3(NTILES / 2, NB), 256, smem_bytes>>>(out);
}